// round 10
// baseline (speedup 1.0000x reference)
#include <cuda_runtime.h>
#include <cuda_fp16.h>
#include <cstdint>

// Problem constants (shapes fixed by the reference)
constexpr int NF = 512;   // input features
constexpr int NH = 256;   // hidden
constexpr int NC = 64;    // classes
constexpr int NNODE = 100000;
constexpr int EMAX = 3200000;

// Scratch (allocation-free rule: __device__ globals)
__device__ __half g_xw1[(size_t)NNODE * NH];  // x @ W1 (fp16)
__device__ __half g_h[(size_t)NNODE * NH];    // spmm1 out / h (fp16)
__device__ __half g_hw2[(size_t)NNODE * NC];  // h @ W2 (fp16)
__device__ int    g_rowptr[NNODE + 1];
__device__ int    g_cursor[NNODE];
__device__ int2   g_edges[EMAX];              // (col, val-bits) sorted by row
__device__ int    g_bsums[128];

// ---------------------------------------------------------------------------
__device__ __forceinline__ void mma_f16(float c[4], const uint32_t a[4], const uint32_t b[2]) {
    asm volatile(
        "mma.sync.aligned.m16n8k16.row.col.f32.f16.f16.f32 "
        "{%0,%1,%2,%3}, {%4,%5,%6,%7}, {%8,%9}, {%0,%1,%2,%3};"
        : "+f"(c[0]), "+f"(c[1]), "+f"(c[2]), "+f"(c[3])
        : "r"(a[0]), "r"(a[1]), "r"(a[2]), "r"(a[3]), "r"(b[0]), "r"(b[1]));
}

__device__ __forceinline__ void stcs_u2(uint2* p, uint2 v) {
    asm volatile("st.global.cs.v2.u32 [%0], {%1,%2};"
                 :: "l"(p), "r"(v.x), "r"(v.y) : "memory");
}

// ---------------------------------------------------------------------------
// CSR build
__global__ void k_zero_csr() {
    int i = blockIdx.x * blockDim.x + threadIdx.x;
    if (i <= NNODE) g_rowptr[i] = 0;
    if (i < NNODE) g_cursor[i] = 0;
}

__global__ void k_hist(const int* __restrict__ rows, int E) {
    int e = blockIdx.x * blockDim.x + threadIdx.x;
    if (e < E) atomicAdd(&g_rowptr[rows[e] + 1], 1);
}

// inclusive block scan: 1024 elements per block (256 threads x 4)
__global__ void k_scan_block(int* __restrict__ d, int L, int* __restrict__ bsums) {
    __shared__ int warpsum[8];
    const int t = threadIdx.x, lane = t & 31, wid = t >> 5;
    const int base = blockIdx.x * 1024 + t * 4;
    int v0 = 0, v1 = 0, v2 = 0, v3 = 0;
    if (base + 3 < L) {
        int4 x = *(const int4*)(d + base);
        v0 = x.x; v1 = x.y; v2 = x.z; v3 = x.w;
    } else {
        if (base < L) v0 = d[base];
        if (base + 1 < L) v1 = d[base + 1];
        if (base + 2 < L) v2 = d[base + 2];
    }
    v1 += v0; v2 += v1; v3 += v2;
    int inc = v3;
#pragma unroll
    for (int o = 1; o < 32; o <<= 1) {
        int n = __shfl_up_sync(0xffffffffu, inc, o);
        if (lane >= o) inc += n;
    }
    if (lane == 31) warpsum[wid] = inc;
    __syncthreads();
    if (wid == 0) {
        int s = (lane < 8) ? warpsum[lane] : 0;
#pragma unroll
        for (int o = 1; o < 8; o <<= 1) {
            int n = __shfl_up_sync(0xffffffffu, s, o);
            if (lane >= o) s += n;
        }
        if (lane < 8) warpsum[lane] = s;
    }
    __syncthreads();
    int off = inc - v3;
    if (wid > 0) off += warpsum[wid - 1];
    v0 += off; v1 += off; v2 += off; v3 += off;
    if (base + 3 < L) {
        *(int4*)(d + base) = make_int4(v0, v1, v2, v3);
    } else {
        if (base < L) d[base] = v0;
        if (base + 1 < L) d[base + 1] = v1;
        if (base + 2 < L) d[base + 2] = v2;
    }
    if (t == 255) bsums[blockIdx.x] = v3;
}

__global__ void k_scan_sums(int* __restrict__ bsums, int nb) {
    __shared__ int ws[4];
    const int t = threadIdx.x, lane = t & 31, wid = t >> 5;
    int v = (t < nb) ? bsums[t] : 0;
    int inc = v;
#pragma unroll
    for (int o = 1; o < 32; o <<= 1) {
        int n = __shfl_up_sync(0xffffffffu, inc, o);
        if (lane >= o) inc += n;
    }
    if (lane == 31) ws[wid] = inc;
    __syncthreads();
    if (t == 0) {
        int run = 0;
#pragma unroll
        for (int i = 0; i < 4; i++) { int tmp = ws[i]; ws[i] = run; run += tmp; }
    }
    __syncthreads();
    int excl = inc - v + ws[wid];
    if (t < nb) bsums[t] = excl;
}

__global__ void k_scan_add(int* __restrict__ d, int L) {
    const int b = blockIdx.x;
    if (b == 0) return;
    const int add = g_bsums[b];
    const int base = b * 1024 + threadIdx.x * 4;
#pragma unroll
    for (int j = 0; j < 4; j++)
        if (base + j < L) d[base + j] += add;
}

__global__ void k_scatter(const int* __restrict__ rows, const int* __restrict__ cols,
                          const float* __restrict__ vals, int E) {
    int e = blockIdx.x * blockDim.x + threadIdx.x;
    if (e >= E) return;
    int r = rows[e];
    int idx = g_rowptr[r] + atomicAdd(&g_cursor[r], 1);
    g_edges[idx] = make_int2(cols[e], __float_as_int(vals[e]));
}

// ---------------------------------------------------------------------------
// FP16 GEMM (m16n8k16, fp32 accum): C[:, colOff:colOff+128] = A @ B[:, ...].
// BM=128 x BN=128 x BK=32, 256 threads (2x4 warps). A fp32, C fp16.
__global__ __launch_bounds__(256) void f16_gemm1_cols(
        const float* __restrict__ A, const float* __restrict__ B,
        __half* __restrict__ C, int M, int N, int K, int colOff) {
    constexpr int BM = 128;
    constexpr int BN = 128;
    constexpr int BK = 32;
    constexpr int WM = 64;   // 2 warps in M
    constexpr int WN = 32;   // 4 warps in N
    constexpr int MFR = 4;
    constexpr int NFR = 4;
    constexpr int AS2 = 20;
    constexpr int BS2 = BN + 8;

    __shared__ __align__(16) __half2 As[BM][AS2];
    __shared__ __align__(16) __half2 Bs[BK / 2][BS2];

    const int tid  = threadIdx.x;
    const int warp = tid >> 5;
    const int lane = tid & 31;
    const int wm = (warp & 1) * WM;
    const int wn = (warp >> 1) * WN;
    const int rowBase = blockIdx.y * BM;
    const int colBase = colOff;

    float acc[MFR][NFR][4];
#pragma unroll
    for (int i = 0; i < MFR; i++)
#pragma unroll
        for (int j = 0; j < NFR; j++)
#pragma unroll
            for (int q = 0; q < 4; q++) acc[i][j][q] = 0.f;

    // A: 128 rows x 32 cols fp32; 2 threads/row, 16 floats each
    const int arow = tid >> 1;
    const int acol0 = (tid & 1) * 16;
    // B: 32 rows x 128 cols fp32; 8 threads/row, 4 float4 each
    const int brow = tid >> 3;
    const int bf40 = tid & 7;

    for (int k0 = 0; k0 < K; k0 += BK) {
        {
            const int gr = rowBase + arow;
            const float* ap = A + (size_t)gr * K + k0 + acol0;
            __half2 h[8];
#pragma unroll
            for (int i = 0; i < 4; i++) {
                float4 a = make_float4(0.f, 0.f, 0.f, 0.f);
                if (gr < M) a = *(const float4*)(ap + i * 4);
                h[i * 2 + 0] = __floats2half2_rn(a.x, a.y);
                h[i * 2 + 1] = __floats2half2_rn(a.z, a.w);
            }
            *(uint4*)&As[arow][acol0 / 2 + 0] = *(const uint4*)&h[0];
            *(uint4*)&As[arow][acol0 / 2 + 4] = *(const uint4*)&h[4];
        }
        {
            const float* bp = B + (size_t)(k0 + brow) * N + colBase;
            __half* bsh = (__half*)&Bs[brow >> 1][0];
            const int hsel = brow & 1;
#pragma unroll
            for (int i = 0; i < 4; i++) {
                const int n = (bf40 + i * 8) * 4;
                float4 b = *(const float4*)(bp + n);
                bsh[(n + 0) * 2 + hsel] = __float2half_rn(b.x);
                bsh[(n + 1) * 2 + hsel] = __float2half_rn(b.y);
                bsh[(n + 2) * 2 + hsel] = __float2half_rn(b.z);
                bsh[(n + 3) * 2 + hsel] = __float2half_rn(b.w);
            }
        }
        __syncthreads();

#pragma unroll
        for (int ks = 0; ks < BK / 16; ks++) {
            uint32_t afr[MFR][4];
            uint32_t bfr[NFR][2];
            const int ar = wm + (lane >> 2);
            const int kb = ks * 8 + (lane & 3);
#pragma unroll
            for (int mi = 0; mi < MFR; mi++) {
                afr[mi][0] = *(const uint32_t*)&As[ar + mi * 16 + 0][kb + 0];
                afr[mi][1] = *(const uint32_t*)&As[ar + mi * 16 + 8][kb + 0];
                afr[mi][2] = *(const uint32_t*)&As[ar + mi * 16 + 0][kb + 4];
                afr[mi][3] = *(const uint32_t*)&As[ar + mi * 16 + 8][kb + 4];
            }
            const int bc = wn + (lane >> 2);
#pragma unroll
            for (int ni = 0; ni < NFR; ni++) {
                bfr[ni][0] = *(const uint32_t*)&Bs[kb + 0][bc + ni * 8];
                bfr[ni][1] = *(const uint32_t*)&Bs[kb + 4][bc + ni * 8];
            }
#pragma unroll
            for (int mi = 0; mi < MFR; mi++)
#pragma unroll
                for (int ni = 0; ni < NFR; ni++)
                    mma_f16(acc[mi][ni], afr[mi], bfr[ni]);
        }
        __syncthreads();
    }

#pragma unroll
    for (int mi = 0; mi < MFR; mi++) {
#pragma unroll
        for (int ni = 0; ni < NFR; ni++) {
            const int r0 = rowBase + wm + mi * 16 + (lane >> 2);
            const int c0 = colBase + wn + ni * 8 + 2 * (lane & 3);
            if (r0 < M)
                *(__half2*)(C + (size_t)r0 * N + c0) =
                    __floats2half2_rn(acc[mi][ni][0], acc[mi][ni][1]);
            if (r0 + 8 < M)
                *(__half2*)(C + (size_t)(r0 + 8) * N + c0) =
                    __floats2half2_rn(acc[mi][ni][2], acc[mi][ni][3]);
        }
    }
}

// FP16 GEMM, fp16 A (direct copy), BM=128, BK=32, 256 threads. (GEMM2)
template<int BN, int WARPS_M, int WARPS_N>
__global__ __launch_bounds__(256) void f16_gemm_f16in(
        const __half* __restrict__ A, const float* __restrict__ B,
        __half* __restrict__ C, int M, int N, int K) {
    constexpr int BM = 128;
    constexpr int BK = 32;
    constexpr int WM = BM / WARPS_M;
    constexpr int WN = BN / WARPS_N;
    constexpr int MFR = WM / 16;
    constexpr int NFR = WN / 8;
    constexpr int AS2 = 20;
    constexpr int BS2 = BN + 8;

    __shared__ __align__(16) __half2 As[BM][AS2];
    __shared__ __align__(16) __half2 Bs[BK / 2][BS2];

    const int tid  = threadIdx.x;
    const int warp = tid >> 5;
    const int lane = tid & 31;
    const int wm = (warp % WARPS_M) * WM;
    const int wn = (warp / WARPS_M) * WN;
    const int rowBase = blockIdx.y * BM;
    const int colBase = blockIdx.x * BN;

    float acc[MFR][NFR][4];
#pragma unroll
    for (int i = 0; i < MFR; i++)
#pragma unroll
        for (int j = 0; j < NFR; j++)
#pragma unroll
            for (int q = 0; q < 4; q++) acc[i][j][q] = 0.f;

    const int arow = tid >> 1;
    const int acolh = (tid & 1) * 16;
    const int brow = tid >> 3;
    const int bf40 = tid & 7;

    for (int k0 = 0; k0 < K; k0 += BK) {
        {
            const int gr = rowBase + arow;
            const __half* ap = A + (size_t)gr * K + k0 + acolh;
            uint4 q0 = make_uint4(0, 0, 0, 0), q1 = make_uint4(0, 0, 0, 0);
            if (gr < M) {
                q0 = *(const uint4*)ap;
                q1 = *(const uint4*)(ap + 8);
            }
            *(uint4*)&As[arow][acolh / 2 + 0] = q0;
            *(uint4*)&As[arow][acolh / 2 + 4] = q1;
        }
        {
            const float* bp = B + (size_t)(k0 + brow) * N + colBase;
            __half* bsh = (__half*)&Bs[brow >> 1][0];
            const int hsel = brow & 1;
#pragma unroll
            for (int i = 0; i < BN / 32; i++) {
                const int n = (bf40 + i * 8) * 4;
                float4 b = *(const float4*)(bp + n);
                bsh[(n + 0) * 2 + hsel] = __float2half_rn(b.x);
                bsh[(n + 1) * 2 + hsel] = __float2half_rn(b.y);
                bsh[(n + 2) * 2 + hsel] = __float2half_rn(b.z);
                bsh[(n + 3) * 2 + hsel] = __float2half_rn(b.w);
            }
        }
        __syncthreads();

#pragma unroll
        for (int ks = 0; ks < BK / 16; ks++) {
            uint32_t afr[MFR][4];
            uint32_t bfr[NFR][2];
            const int ar = wm + (lane >> 2);
            const int kb = ks * 8 + (lane & 3);
#pragma unroll
            for (int mi = 0; mi < MFR; mi++) {
                afr[mi][0] = *(const uint32_t*)&As[ar + mi * 16 + 0][kb + 0];
                afr[mi][1] = *(const uint32_t*)&As[ar + mi * 16 + 8][kb + 0];
                afr[mi][2] = *(const uint32_t*)&As[ar + mi * 16 + 0][kb + 4];
                afr[mi][3] = *(const uint32_t*)&As[ar + mi * 16 + 8][kb + 4];
            }
            const int bc = wn + (lane >> 2);
#pragma unroll
            for (int ni = 0; ni < NFR; ni++) {
                bfr[ni][0] = *(const uint32_t*)&Bs[kb + 0][bc + ni * 8];
                bfr[ni][1] = *(const uint32_t*)&Bs[kb + 4][bc + ni * 8];
            }
#pragma unroll
            for (int mi = 0; mi < MFR; mi++)
#pragma unroll
                for (int ni = 0; ni < NFR; ni++)
                    mma_f16(acc[mi][ni], afr[mi], bfr[ni]);
        }
        __syncthreads();
    }

#pragma unroll
    for (int mi = 0; mi < MFR; mi++) {
#pragma unroll
        for (int ni = 0; ni < NFR; ni++) {
            const int r0 = rowBase + wm + mi * 16 + (lane >> 2);
            const int c0 = colBase + wn + ni * 8 + 2 * (lane & 3);
            if (r0 < M)
                *(__half2*)(C + (size_t)r0 * N + c0) =
                    __floats2half2_rn(acc[mi][ni][0], acc[mi][ni][1]);
            if (r0 + 8 < M)
                *(__half2*)(C + (size_t)(r0 + 8) * N + c0) =
                    __floats2half2_rn(acc[mi][ni][2], acc[mi][ni][3]);
        }
    }
}

// ---------------------------------------------------------------------------
// CSR SpMM, 128-feature chunk of F=256, fp16 source (R7 inner-loop form).
// One warp per row; lane owns 4 halfs (uint2) in the chunk. off2 in uint2
// units within a row (0 or 32). Fused bias+relu; streaming fp16 output.
__global__ void spmm_csr_f256h_chunk(const __half* __restrict__ X,
                                     const float* __restrict__ bias,
                                     __half* __restrict__ Y, int off2) {
    const int r = (blockIdx.x * blockDim.x + threadIdx.x) >> 5;
    const int lane = threadIdx.x & 31;
    if (r >= NNODE) return;
    const int start = g_rowptr[r];
    const int end   = g_rowptr[r + 1];
    float acc[4];
#pragma unroll
    for (int i = 0; i < 4; i++) acc[i] = 0.f;
    const uint2* Xb = (const uint2*)X + off2 + lane;  // row stride = 64 uint2
    for (int base = start; base < end; base += 32) {
        const int m = min(32, end - base);
        int2 ev = make_int2(0, 0);
        if (lane < m) ev = g_edges[base + lane];
#pragma unroll 4
        for (int j = 0; j < m; j++) {
            const int   cj = __shfl_sync(0xffffffffu, ev.x, j);
            const float vj = __int_as_float(__shfl_sync(0xffffffffu, ev.y, j));
            uint2 q = __ldg(Xb + (size_t)cj * 64);
            float2 f0 = __half22float2(*(const __half2*)&q.x);
            float2 f1 = __half22float2(*(const __half2*)&q.y);
            acc[0] = fmaf(vj, f0.x, acc[0]);
            acc[1] = fmaf(vj, f0.y, acc[1]);
            acc[2] = fmaf(vj, f1.x, acc[2]);
            acc[3] = fmaf(vj, f1.y, acc[3]);
        }
    }
    float4 bb = __ldg((const float4*)bias + off2 + lane);
    __half2 o0 = __floats2half2_rn(fmaxf(acc[0] + bb.x, 0.f), fmaxf(acc[1] + bb.y, 0.f));
    __half2 o1 = __floats2half2_rn(fmaxf(acc[2] + bb.z, 0.f), fmaxf(acc[3] + bb.w, 0.f));
    uint2 ov = make_uint2(*(const uint32_t*)&o0, *(const uint32_t*)&o1);
    stcs_u2((uint2*)Y + (size_t)r * 64 + off2 + lane, ov);
}

// CSR SpMM F=64 (fp16 source) fused with bias + log_softmax (R7 form).
__global__ void spmm_csr_f64h_ls(const __half* __restrict__ X, const float* __restrict__ bias,
                                 float* __restrict__ out) {
    const int r = (blockIdx.x * blockDim.x + threadIdx.x) >> 5;
    const int lane = threadIdx.x & 31;
    if (r >= NNODE) return;
    const int start = g_rowptr[r];
    const int end   = g_rowptr[r + 1];
    float2 acc = make_float2(0.f, 0.f);
    const uint32_t* Xb = (const uint32_t*)X + lane;
    for (int base = start; base < end; base += 32) {
        const int m = min(32, end - base);
        int2 ev = make_int2(0, 0);
        if (lane < m) ev = g_edges[base + lane];
#pragma unroll 4
        for (int j = 0; j < m; j++) {
            const int   cj = __shfl_sync(0xffffffffu, ev.x, j);
            const float vj = __int_as_float(__shfl_sync(0xffffffffu, ev.y, j));
            uint32_t q = __ldg(Xb + (size_t)cj * 32);
            float2 xs = __half22float2(*(const __half2*)&q);
            acc.x = fmaf(vj, xs.x, acc.x);
            acc.y = fmaf(vj, xs.y, acc.y);
        }
    }
    float2 bb = __ldg((const float2*)bias + lane);
    float v0 = acc.x + bb.x;
    float v1 = acc.y + bb.y;
    float mx = fmaxf(v0, v1);
#pragma unroll
    for (int o = 16; o; o >>= 1) mx = fmaxf(mx, __shfl_xor_sync(0xffffffffu, mx, o));
    float s = __expf(v0 - mx) + __expf(v1 - mx);
#pragma unroll
    for (int o = 16; o; o >>= 1) s += __shfl_xor_sync(0xffffffffu, s, o);
    float lse = mx + __logf(s);
    *(float2*)(out + (size_t)r * 64 + lane * 2) = make_float2(v0 - lse, v1 - lse);
}

// ---------------------------------------------------------------------------
extern "C" void kernel_launch(void* const* d_in, const int* in_sizes, int n_in,
                              void* d_out, int out_size) {
    const float* x    = (const float*)d_in[0];
    const int*   erow = (const int*)d_in[1];
    const int*   ecol = (const int*)d_in[2];
    const float* eval_ = (const float*)d_in[3];
    const float* W1   = (const float*)d_in[4];
    const float* b1   = (const float*)d_in[5];
    const float* W2   = (const float*)d_in[6];
    const float* b2   = (const float*)d_in[7];
    float* out = (float*)d_out;

    const int E = in_sizes[1];
    const int M = in_sizes[0] / NF;  // 100000

    __half *xw1, *h, *hw2;
    int *rowptr, *bsums;
    cudaGetSymbolAddress((void**)&xw1, g_xw1);
    cudaGetSymbolAddress((void**)&h, g_h);
    cudaGetSymbolAddress((void**)&hw2, g_hw2);
    cudaGetSymbolAddress((void**)&rowptr, g_rowptr);
    cudaGetSymbolAddress((void**)&bsums, g_bsums);

    const int L = NNODE + 1;
    const int nscan = (L + 1023) / 1024;  // 98
    const int spmmBlocks = (NNODE * 32 + 255) / 256;

    // One-time side resources (host-side only; no device memory involved).
    static cudaStream_t s2 = nullptr, s3 = nullptr;
    static cudaEvent_t evFork = nullptr, evCSR = nullptr;
    static cudaEvent_t evG1a = nullptr, evG1b = nullptr, evPipe = nullptr;
    if (!s2) {
        cudaStreamCreateWithFlags(&s2, cudaStreamNonBlocking);
        cudaStreamCreateWithFlags(&s3, cudaStreamNonBlocking);
        cudaEventCreateWithFlags(&evFork, cudaEventDisableTiming);
        cudaEventCreateWithFlags(&evCSR, cudaEventDisableTiming);
        cudaEventCreateWithFlags(&evG1a, cudaEventDisableTiming);
        cudaEventCreateWithFlags(&evG1b, cudaEventDisableTiming);
        cudaEventCreateWithFlags(&evPipe, cudaEventDisableTiming);
    }

    // Fork s2: CSR build concurrent with GEMM1a/1b on the main stream.
    cudaEventRecord(evFork, 0);
    cudaStreamWaitEvent(s2, evFork, 0);

    // --- CSR build (stream s2) ---
    k_zero_csr<<<(NNODE + 256) / 256, 256, 0, s2>>>();
    k_hist<<<(E + 255) / 256, 256, 0, s2>>>(erow, E);
    k_scan_block<<<nscan, 256, 0, s2>>>(rowptr, L, bsums);
    k_scan_sums<<<1, 128, 0, s2>>>(bsums, nscan);
    k_scan_add<<<nscan, 256, 0, s2>>>(rowptr, L);
    k_scatter<<<(E + 255) / 256, 256, 0, s2>>>(erow, ecol, eval_, E);
    cudaEventRecord(evCSR, s2);

    // --- layer 1 GEMM, two 128-col halves (main stream) ---
    f16_gemm1_cols<<<dim3(1, (M + 127) / 128), 256>>>(x, W1, xw1, M, NH, NF, 0);
    cudaEventRecord(evG1a, 0);
    f16_gemm1_cols<<<dim3(1, (M + 127) / 128), 256>>>(x, W1, xw1, M, NH, NF, 128);
    cudaEventRecord(evG1b, 0);

    // --- spmm1 pipeline (stream s3): chunk a after {G1a, CSR}, chunk b after G1b ---
    cudaStreamWaitEvent(s3, evG1a, 0);
    cudaStreamWaitEvent(s3, evCSR, 0);
    spmm_csr_f256h_chunk<<<spmmBlocks, 256, 0, s3>>>(xw1, b1, h, 0);
    cudaStreamWaitEvent(s3, evG1b, 0);
    spmm_csr_f256h_chunk<<<spmmBlocks, 256, 0, s3>>>(xw1, b1, h, 32);
    cudaEventRecord(evPipe, s3);

    // --- join back to main stream ---
    cudaStreamWaitEvent(0, evPipe, 0);

    // layer 2: HW2 = h @ W2  (fp16 tensor cores, fp16 A direct)
    f16_gemm_f16in<64, 4, 2><<<dim3(NC / 64, (M + 127) / 128), 256>>>(h, W2, hw2, M, NC, NH);

    // spmm2 (CSR gather, fp16 source) + fused bias + log_softmax
    spmm_csr_f64h_ls<<<spmmBlocks, 256>>>(hw2, b2, out);
}

// round 11
// speedup vs baseline: 1.2683x; 1.2683x over previous
#include <cuda_runtime.h>
#include <cuda_fp16.h>
#include <cstdint>

// Problem constants (shapes fixed by the reference)
constexpr int NF = 512;   // input features
constexpr int NH = 256;   // hidden
constexpr int NC = 64;    // classes
constexpr int NNODE = 100000;
constexpr int EMAX = 3200000;

// Scratch (allocation-free rule: __device__ globals)
__device__ __half g_xw1[(size_t)NNODE * NH];  // x @ W1 (fp16)
__device__ __half g_h[(size_t)NNODE * NH];    // spmm1 out / h (fp16)
__device__ __half g_hw2[(size_t)NNODE * NC];  // h @ W2 (fp16)
__device__ int    g_rowptr[NNODE + 1];
__device__ int    g_cursor[NNODE];
__device__ int2   g_edges[EMAX];              // (col, val-bits) sorted by row
__device__ int    g_bsums[128];

// ---------------------------------------------------------------------------
__device__ __forceinline__ void mma_f16(float c[4], const uint32_t a[4], const uint32_t b[2]) {
    asm volatile(
        "mma.sync.aligned.m16n8k16.row.col.f32.f16.f16.f32 "
        "{%0,%1,%2,%3}, {%4,%5,%6,%7}, {%8,%9}, {%0,%1,%2,%3};"
        : "+f"(c[0]), "+f"(c[1]), "+f"(c[2]), "+f"(c[3])
        : "r"(a[0]), "r"(a[1]), "r"(a[2]), "r"(a[3]), "r"(b[0]), "r"(b[1]));
}

__device__ __forceinline__ void stcs_u4(uint4* p, uint4 v) {
    asm volatile("st.global.cs.v4.u32 [%0], {%1,%2,%3,%4};"
                 :: "l"(p), "r"(v.x), "r"(v.y), "r"(v.z), "r"(v.w) : "memory");
}

// ---------------------------------------------------------------------------
// CSR build
__global__ void k_zero_csr() {
    int i = blockIdx.x * blockDim.x + threadIdx.x;
    if (i <= NNODE) g_rowptr[i] = 0;
    if (i < NNODE) g_cursor[i] = 0;
}

__global__ void k_hist(const int* __restrict__ rows, int E) {
    int e = blockIdx.x * blockDim.x + threadIdx.x;
    if (e < E) atomicAdd(&g_rowptr[rows[e] + 1], 1);
}

// inclusive block scan: 1024 elements per block (256 threads x 4)
__global__ void k_scan_block(int* __restrict__ d, int L, int* __restrict__ bsums) {
    __shared__ int warpsum[8];
    const int t = threadIdx.x, lane = t & 31, wid = t >> 5;
    const int base = blockIdx.x * 1024 + t * 4;
    int v0 = 0, v1 = 0, v2 = 0, v3 = 0;
    if (base + 3 < L) {
        int4 x = *(const int4*)(d + base);
        v0 = x.x; v1 = x.y; v2 = x.z; v3 = x.w;
    } else {
        if (base < L) v0 = d[base];
        if (base + 1 < L) v1 = d[base + 1];
        if (base + 2 < L) v2 = d[base + 2];
    }
    v1 += v0; v2 += v1; v3 += v2;
    int inc = v3;
#pragma unroll
    for (int o = 1; o < 32; o <<= 1) {
        int n = __shfl_up_sync(0xffffffffu, inc, o);
        if (lane >= o) inc += n;
    }
    if (lane == 31) warpsum[wid] = inc;
    __syncthreads();
    if (wid == 0) {
        int s = (lane < 8) ? warpsum[lane] : 0;
#pragma unroll
        for (int o = 1; o < 8; o <<= 1) {
            int n = __shfl_up_sync(0xffffffffu, s, o);
            if (lane >= o) s += n;
        }
        if (lane < 8) warpsum[lane] = s;
    }
    __syncthreads();
    int off = inc - v3;
    if (wid > 0) off += warpsum[wid - 1];
    v0 += off; v1 += off; v2 += off; v3 += off;
    if (base + 3 < L) {
        *(int4*)(d + base) = make_int4(v0, v1, v2, v3);
    } else {
        if (base < L) d[base] = v0;
        if (base + 1 < L) d[base + 1] = v1;
        if (base + 2 < L) d[base + 2] = v2;
    }
    if (t == 255) bsums[blockIdx.x] = v3;
}

__global__ void k_scan_sums(int* __restrict__ bsums, int nb) {
    __shared__ int ws[4];
    const int t = threadIdx.x, lane = t & 31, wid = t >> 5;
    int v = (t < nb) ? bsums[t] : 0;
    int inc = v;
#pragma unroll
    for (int o = 1; o < 32; o <<= 1) {
        int n = __shfl_up_sync(0xffffffffu, inc, o);
        if (lane >= o) inc += n;
    }
    if (lane == 31) ws[wid] = inc;
    __syncthreads();
    if (t == 0) {
        int run = 0;
#pragma unroll
        for (int i = 0; i < 4; i++) { int tmp = ws[i]; ws[i] = run; run += tmp; }
    }
    __syncthreads();
    int excl = inc - v + ws[wid];
    if (t < nb) bsums[t] = excl;
}

__global__ void k_scan_add(int* __restrict__ d, int L) {
    const int b = blockIdx.x;
    if (b == 0) return;
    const int add = g_bsums[b];
    const int base = b * 1024 + threadIdx.x * 4;
#pragma unroll
    for (int j = 0; j < 4; j++)
        if (base + j < L) d[base + j] += add;
}

__global__ void k_scatter(const int* __restrict__ rows, const int* __restrict__ cols,
                          const float* __restrict__ vals, int E) {
    int e = blockIdx.x * blockDim.x + threadIdx.x;
    if (e >= E) return;
    int r = rows[e];
    int idx = g_rowptr[r] + atomicAdd(&g_cursor[r], 1);
    g_edges[idx] = make_int2(cols[e], __float_as_int(vals[e]));
}

// ---------------------------------------------------------------------------
// FP16 GEMM (m16n8k16, fp32 accum), BM=128 x BN=256 x BK=32, 512 threads.
// A fp32 [M,512] read ONCE. Register double-buffered: next k-tile's LDGs are
// issued right after the first sync so they overlap the MMA phase.
__global__ __launch_bounds__(512) void f16_gemm1(
        const float* __restrict__ A, const float* __restrict__ B,
        __half* __restrict__ C, int M, int N, int K) {
    constexpr int BM = 128;
    constexpr int BN = 256;
    constexpr int BK = 32;
    constexpr int WM = 32;
    constexpr int WN = 64;
    constexpr int MFR = 2;
    constexpr int NFR = 8;
    constexpr int AS2 = 20;
    constexpr int BS2 = BN + 8;

    __shared__ __align__(16) __half2 As[BM][AS2];
    __shared__ __align__(16) __half2 Bs[BK / 2][BS2];

    const int tid  = threadIdx.x;
    const int warp = tid >> 5;
    const int lane = tid & 31;
    const int wm = (warp & 3) * WM;
    const int wn = (warp >> 2) * WN;
    const int rowBase = blockIdx.y * BM;

    float acc[MFR][NFR][4];
#pragma unroll
    for (int i = 0; i < MFR; i++)
#pragma unroll
        for (int j = 0; j < NFR; j++)
#pragma unroll
            for (int q = 0; q < 4; q++) acc[i][j][q] = 0.f;

    const int arow = tid >> 2;
    const int acol0 = (tid & 3) * 8;
    const int brow = tid >> 4;
    const int bf40 = tid & 15;
    const int gr = rowBase + arow;
    const bool aok = (gr < M);
    const float* aBase = A + (size_t)gr * K + acol0;
    const float* bBase = B + (size_t)brow * N;

    // --- prologue: prefetch k0 = 0 ---
    float4 pa0 = make_float4(0.f, 0.f, 0.f, 0.f);
    float4 pa1 = make_float4(0.f, 0.f, 0.f, 0.f);
    float4 pb[4];
    if (aok) { pa0 = *(const float4*)aBase; pa1 = *(const float4*)(aBase + 4); }
#pragma unroll
    for (int i = 0; i < 4; i++)
        pb[i] = *(const float4*)(bBase + (bf40 + i * 16) * 4);

    for (int k0 = 0; k0 < K; k0 += BK) {
        // --- store prefetched tile to smem (with f32->f16 conversion) ---
        {
            __half2 h[4];
            h[0] = __floats2half2_rn(pa0.x, pa0.y);
            h[1] = __floats2half2_rn(pa0.z, pa0.w);
            h[2] = __floats2half2_rn(pa1.x, pa1.y);
            h[3] = __floats2half2_rn(pa1.z, pa1.w);
            *(uint4*)&As[arow][acol0 / 2] = *(const uint4*)h;
        }
        {
            __half* bsh = (__half*)&Bs[brow >> 1][0];
            const int hsel = brow & 1;
#pragma unroll
            for (int i = 0; i < 4; i++) {
                const int n = (bf40 + i * 16) * 4;
                bsh[(n + 0) * 2 + hsel] = __float2half_rn(pb[i].x);
                bsh[(n + 1) * 2 + hsel] = __float2half_rn(pb[i].y);
                bsh[(n + 2) * 2 + hsel] = __float2half_rn(pb[i].z);
                bsh[(n + 3) * 2 + hsel] = __float2half_rn(pb[i].w);
            }
        }
        __syncthreads();

        // --- prefetch next tile (overlaps the MMA phase below) ---
        const int kn = k0 + BK;
        if (kn < K) {
            if (aok) {
                pa0 = *(const float4*)(aBase + kn);
                pa1 = *(const float4*)(aBase + kn + 4);
            }
            const float* bp = bBase + (size_t)kn * N;
#pragma unroll
            for (int i = 0; i < 4; i++)
                pb[i] = *(const float4*)(bp + (bf40 + i * 16) * 4);
        }

        // --- MMA phase ---
#pragma unroll
        for (int ks = 0; ks < BK / 16; ks++) {
            uint32_t afr[MFR][4];
            uint32_t bfr[NFR][2];
            const int ar = wm + (lane >> 2);
            const int kb = ks * 8 + (lane & 3);
#pragma unroll
            for (int mi = 0; mi < MFR; mi++) {
                afr[mi][0] = *(const uint32_t*)&As[ar + mi * 16 + 0][kb + 0];
                afr[mi][1] = *(const uint32_t*)&As[ar + mi * 16 + 8][kb + 0];
                afr[mi][2] = *(const uint32_t*)&As[ar + mi * 16 + 0][kb + 4];
                afr[mi][3] = *(const uint32_t*)&As[ar + mi * 16 + 8][kb + 4];
            }
            const int bc = wn + (lane >> 2);
#pragma unroll
            for (int ni = 0; ni < NFR; ni++) {
                bfr[ni][0] = *(const uint32_t*)&Bs[kb + 0][bc + ni * 8];
                bfr[ni][1] = *(const uint32_t*)&Bs[kb + 4][bc + ni * 8];
            }
#pragma unroll
            for (int mi = 0; mi < MFR; mi++)
#pragma unroll
                for (int ni = 0; ni < NFR; ni++)
                    mma_f16(acc[mi][ni], afr[mi], bfr[ni]);
        }
        __syncthreads();
    }

#pragma unroll
    for (int mi = 0; mi < MFR; mi++) {
#pragma unroll
        for (int ni = 0; ni < NFR; ni++) {
            const int r0 = rowBase + wm + mi * 16 + (lane >> 2);
            const int c0 = wn + ni * 8 + 2 * (lane & 3);
            if (r0 < M)
                *(__half2*)(C + (size_t)r0 * N + c0) =
                    __floats2half2_rn(acc[mi][ni][0], acc[mi][ni][1]);
            if (r0 + 8 < M)
                *(__half2*)(C + (size_t)(r0 + 8) * N + c0) =
                    __floats2half2_rn(acc[mi][ni][2], acc[mi][ni][3]);
        }
    }
}

// FP16 GEMM, fp16 A (direct copy), BM=128, BK=32, 256 threads. (GEMM2)
template<int BN, int WARPS_M, int WARPS_N>
__global__ __launch_bounds__(256) void f16_gemm_f16in(
        const __half* __restrict__ A, const float* __restrict__ B,
        __half* __restrict__ C, int M, int N, int K) {
    constexpr int BM = 128;
    constexpr int BK = 32;
    constexpr int WM = BM / WARPS_M;
    constexpr int WN = BN / WARPS_N;
    constexpr int MFR = WM / 16;
    constexpr int NFR = WN / 8;
    constexpr int AS2 = 20;
    constexpr int BS2 = BN + 8;

    __shared__ __align__(16) __half2 As[BM][AS2];
    __shared__ __align__(16) __half2 Bs[BK / 2][BS2];

    const int tid  = threadIdx.x;
    const int warp = tid >> 5;
    const int lane = tid & 31;
    const int wm = (warp % WARPS_M) * WM;
    const int wn = (warp / WARPS_M) * WN;
    const int rowBase = blockIdx.y * BM;
    const int colBase = blockIdx.x * BN;

    float acc[MFR][NFR][4];
#pragma unroll
    for (int i = 0; i < MFR; i++)
#pragma unroll
        for (int j = 0; j < NFR; j++)
#pragma unroll
            for (int q = 0; q < 4; q++) acc[i][j][q] = 0.f;

    const int arow = tid >> 1;
    const int acolh = (tid & 1) * 16;
    const int brow = tid >> 3;
    const int bf40 = tid & 7;

    for (int k0 = 0; k0 < K; k0 += BK) {
        {
            const int gr = rowBase + arow;
            const __half* ap = A + (size_t)gr * K + k0 + acolh;
            uint4 q0 = make_uint4(0, 0, 0, 0), q1 = make_uint4(0, 0, 0, 0);
            if (gr < M) {
                q0 = *(const uint4*)ap;
                q1 = *(const uint4*)(ap + 8);
            }
            *(uint4*)&As[arow][acolh / 2 + 0] = q0;
            *(uint4*)&As[arow][acolh / 2 + 4] = q1;
        }
        {
            const float* bp = B + (size_t)(k0 + brow) * N + colBase;
            __half* bsh = (__half*)&Bs[brow >> 1][0];
            const int hsel = brow & 1;
#pragma unroll
            for (int i = 0; i < BN / 32; i++) {
                const int n = (bf40 + i * 8) * 4;
                float4 b = *(const float4*)(bp + n);
                bsh[(n + 0) * 2 + hsel] = __float2half_rn(b.x);
                bsh[(n + 1) * 2 + hsel] = __float2half_rn(b.y);
                bsh[(n + 2) * 2 + hsel] = __float2half_rn(b.z);
                bsh[(n + 3) * 2 + hsel] = __float2half_rn(b.w);
            }
        }
        __syncthreads();

#pragma unroll
        for (int ks = 0; ks < BK / 16; ks++) {
            uint32_t afr[MFR][4];
            uint32_t bfr[NFR][2];
            const int ar = wm + (lane >> 2);
            const int kb = ks * 8 + (lane & 3);
#pragma unroll
            for (int mi = 0; mi < MFR; mi++) {
                afr[mi][0] = *(const uint32_t*)&As[ar + mi * 16 + 0][kb + 0];
                afr[mi][1] = *(const uint32_t*)&As[ar + mi * 16 + 8][kb + 0];
                afr[mi][2] = *(const uint32_t*)&As[ar + mi * 16 + 0][kb + 4];
                afr[mi][3] = *(const uint32_t*)&As[ar + mi * 16 + 8][kb + 4];
            }
            const int bc = wn + (lane >> 2);
#pragma unroll
            for (int ni = 0; ni < NFR; ni++) {
                bfr[ni][0] = *(const uint32_t*)&Bs[kb + 0][bc + ni * 8];
                bfr[ni][1] = *(const uint32_t*)&Bs[kb + 4][bc + ni * 8];
            }
#pragma unroll
            for (int mi = 0; mi < MFR; mi++)
#pragma unroll
                for (int ni = 0; ni < NFR; ni++)
                    mma_f16(acc[mi][ni], afr[mi], bfr[ni]);
        }
        __syncthreads();
    }

#pragma unroll
    for (int mi = 0; mi < MFR; mi++) {
#pragma unroll
        for (int ni = 0; ni < NFR; ni++) {
            const int r0 = rowBase + wm + mi * 16 + (lane >> 2);
            const int c0 = colBase + wn + ni * 8 + 2 * (lane & 3);
            if (r0 < M)
                *(__half2*)(C + (size_t)r0 * N + c0) =
                    __floats2half2_rn(acc[mi][ni][0], acc[mi][ni][1]);
            if (r0 + 8 < M)
                *(__half2*)(C + (size_t)(r0 + 8) * N + c0) =
                    __floats2half2_rn(acc[mi][ni][2], acc[mi][ni][3]);
        }
    }
}

// ---------------------------------------------------------------------------
// CSR SpMM, F=256, fp16 source (R7 form). One warp per row; lane owns 8 halfs.
__global__ void spmm_csr_f256h(const __half* __restrict__ X, const float* __restrict__ bias,
                               __half* __restrict__ Y) {
    const int r = (blockIdx.x * blockDim.x + threadIdx.x) >> 5;
    const int lane = threadIdx.x & 31;
    if (r >= NNODE) return;
    const int start = g_rowptr[r];
    const int end   = g_rowptr[r + 1];
    float acc[8];
#pragma unroll
    for (int i = 0; i < 8; i++) acc[i] = 0.f;
    const uint4* Xb = (const uint4*)X + lane;
    for (int base = start; base < end; base += 32) {
        const int m = min(32, end - base);
        int2 ev = make_int2(0, 0);
        if (lane < m) ev = g_edges[base + lane];
#pragma unroll 4
        for (int j = 0; j < m; j++) {
            const int   cj = __shfl_sync(0xffffffffu, ev.x, j);
            const float vj = __int_as_float(__shfl_sync(0xffffffffu, ev.y, j));
            uint4 q = __ldg(Xb + (size_t)cj * 32);
            const __half2* hp = (const __half2*)&q;
#pragma unroll
            for (int i = 0; i < 4; i++) {
                float2 f = __half22float2(hp[i]);
                acc[i * 2 + 0] = fmaf(vj, f.x, acc[i * 2 + 0]);
                acc[i * 2 + 1] = fmaf(vj, f.y, acc[i * 2 + 1]);
            }
        }
    }
    float4 b0 = __ldg((const float4*)bias + lane * 2);
    float4 b1 = __ldg((const float4*)bias + lane * 2 + 1);
    float bb[8] = {b0.x, b0.y, b0.z, b0.w, b1.x, b1.y, b1.z, b1.w};
    __half2 o[4];
#pragma unroll
    for (int i = 0; i < 4; i++)
        o[i] = __floats2half2_rn(fmaxf(acc[i * 2] + bb[i * 2], 0.f),
                                 fmaxf(acc[i * 2 + 1] + bb[i * 2 + 1], 0.f));
    uint4 ov = *(const uint4*)o;
    stcs_u4((uint4*)Y + (size_t)r * 32 + lane, ov);
}

// CSR SpMM F=64 (fp16 source) fused with bias + log_softmax (R7 form).
__global__ void spmm_csr_f64h_ls(const __half* __restrict__ X, const float* __restrict__ bias,
                                 float* __restrict__ out) {
    const int r = (blockIdx.x * blockDim.x + threadIdx.x) >> 5;
    const int lane = threadIdx.x & 31;
    if (r >= NNODE) return;
    const int start = g_rowptr[r];
    const int end   = g_rowptr[r + 1];
    float2 acc = make_float2(0.f, 0.f);
    const uint32_t* Xb = (const uint32_t*)X + lane;
    for (int base = start; base < end; base += 32) {
        const int m = min(32, end - base);
        int2 ev = make_int2(0, 0);
        if (lane < m) ev = g_edges[base + lane];
#pragma unroll 4
        for (int j = 0; j < m; j++) {
            const int   cj = __shfl_sync(0xffffffffu, ev.x, j);
            const float vj = __int_as_float(__shfl_sync(0xffffffffu, ev.y, j));
            uint32_t q = __ldg(Xb + (size_t)cj * 32);
            float2 xs = __half22float2(*(const __half2*)&q);
            acc.x = fmaf(vj, xs.x, acc.x);
            acc.y = fmaf(vj, xs.y, acc.y);
        }
    }
    float2 bb = __ldg((const float2*)bias + lane);
    float v0 = acc.x + bb.x;
    float v1 = acc.y + bb.y;
    float mx = fmaxf(v0, v1);
#pragma unroll
    for (int o = 16; o; o >>= 1) mx = fmaxf(mx, __shfl_xor_sync(0xffffffffu, mx, o));
    float s = __expf(v0 - mx) + __expf(v1 - mx);
#pragma unroll
    for (int o = 16; o; o >>= 1) s += __shfl_xor_sync(0xffffffffu, s, o);
    float lse = mx + __logf(s);
    *(float2*)(out + (size_t)r * 64 + lane * 2) = make_float2(v0 - lse, v1 - lse);
}

// ---------------------------------------------------------------------------
extern "C" void kernel_launch(void* const* d_in, const int* in_sizes, int n_in,
                              void* d_out, int out_size) {
    const float* x    = (const float*)d_in[0];
    const int*   erow = (const int*)d_in[1];
    const int*   ecol = (const int*)d_in[2];
    const float* eval_ = (const float*)d_in[3];
    const float* W1   = (const float*)d_in[4];
    const float* b1   = (const float*)d_in[5];
    const float* W2   = (const float*)d_in[6];
    const float* b2   = (const float*)d_in[7];
    float* out = (float*)d_out;

    const int E = in_sizes[1];
    const int M = in_sizes[0] / NF;  // 100000

    __half *xw1, *h, *hw2;
    int *rowptr, *bsums;
    cudaGetSymbolAddress((void**)&xw1, g_xw1);
    cudaGetSymbolAddress((void**)&h, g_h);
    cudaGetSymbolAddress((void**)&hw2, g_hw2);
    cudaGetSymbolAddress((void**)&rowptr, g_rowptr);
    cudaGetSymbolAddress((void**)&bsums, g_bsums);

    const int L = NNODE + 1;
    const int nscan = (L + 1023) / 1024;  // 98

    // One-time side resources (host-side only; no device memory involved).
    static cudaStream_t s2 = nullptr;
    static cudaEvent_t evFork = nullptr, evJoin = nullptr;
    if (!s2) {
        cudaStreamCreateWithFlags(&s2, cudaStreamNonBlocking);
        cudaEventCreateWithFlags(&evFork, cudaEventDisableTiming);
        cudaEventCreateWithFlags(&evJoin, cudaEventDisableTiming);
    }

    // Fork: CSR build on s2, concurrent with GEMM1 on the main stream.
    cudaEventRecord(evFork, 0);
    cudaStreamWaitEvent(s2, evFork, 0);

    // --- CSR build (stream s2) ---
    k_zero_csr<<<(NNODE + 256) / 256, 256, 0, s2>>>();
    k_hist<<<(E + 255) / 256, 256, 0, s2>>>(erow, E);
    k_scan_block<<<nscan, 256, 0, s2>>>(rowptr, L, bsums);
    k_scan_sums<<<1, 128, 0, s2>>>(bsums, nscan);
    k_scan_add<<<nscan, 256, 0, s2>>>(rowptr, L);
    k_scatter<<<(E + 255) / 256, 256, 0, s2>>>(erow, ecol, eval_, E);
    cudaEventRecord(evJoin, s2);

    // --- layer 1 GEMM (main stream, concurrent with CSR build) ---
    f16_gemm1<<<dim3(1, (M + 127) / 128), 512>>>(x, W1, xw1, M, NH, NF);

    // Join: spmm1 needs both GEMM1 and the CSR structures.
    cudaStreamWaitEvent(0, evJoin, 0);

    // spmm1 (CSR gather, fp16 source L2-resident) + fused bias/relu
    {
        int blocks = (NNODE * 32 + 255) / 256;
        spmm_csr_f256h<<<blocks, 256>>>(xw1, b1, h);
    }

    // layer 2: HW2 = h @ W2  (fp16 tensor cores, fp16 A direct)
    f16_gemm_f16in<64, 4, 2><<<dim3(NC / 64, (M + 127) / 128), 256>>>(h, W2, hw2, M, NC, NH);

    // spmm2 (CSR gather, fp16 source) + fused bias + log_softmax
    {
        int blocks = (NNODE * 32 + 255) / 256;
        spmm_csr_f64h_ls<<<blocks, 256>>>(hw2, b2, out);
    }
}

// round 12
// speedup vs baseline: 1.2715x; 1.0025x over previous
#include <cuda_runtime.h>
#include <cuda_fp16.h>
#include <cstdint>

// Problem constants (shapes fixed by the reference)
constexpr int NF = 512;   // input features
constexpr int NH = 256;   // hidden
constexpr int NC = 64;    // classes
constexpr int NNODE = 100000;
constexpr int EMAX = 3200000;

// Scratch (allocation-free rule: __device__ globals)
__device__ __half g_xw1[(size_t)NNODE * NH];  // x @ W1 (fp16)
__device__ __half g_h[(size_t)NNODE * NH];    // spmm1 out / h (fp16)
__device__ __half g_hw2[(size_t)NNODE * NC];  // h @ W2 (fp16)
__device__ int    g_rowptr[NNODE + 1];
__device__ int    g_cursor[NNODE];
__device__ int2   g_edges[EMAX];              // (col, val-bits) sorted by row
__device__ int    g_bsums[128];

// ---------------------------------------------------------------------------
__device__ __forceinline__ void mma_f16(float c[4], const uint32_t a[4], const uint32_t b[2]) {
    asm volatile(
        "mma.sync.aligned.m16n8k16.row.col.f32.f16.f16.f32 "
        "{%0,%1,%2,%3}, {%4,%5,%6,%7}, {%8,%9}, {%0,%1,%2,%3};"
        : "+f"(c[0]), "+f"(c[1]), "+f"(c[2]), "+f"(c[3])
        : "r"(a[0]), "r"(a[1]), "r"(a[2]), "r"(a[3]), "r"(b[0]), "r"(b[1]));
}

__device__ __forceinline__ void stcs_u4(uint4* p, uint4 v) {
    asm volatile("st.global.cs.v4.u32 [%0], {%1,%2,%3,%4};"
                 :: "l"(p), "r"(v.x), "r"(v.y), "r"(v.z), "r"(v.w) : "memory");
}

// ---------------------------------------------------------------------------
// CSR build
__global__ void k_zero_csr() {
    int i = blockIdx.x * blockDim.x + threadIdx.x;
    if (i <= NNODE) g_rowptr[i] = 0;
    if (i < NNODE) g_cursor[i] = 0;
}

__global__ void k_hist(const int* __restrict__ rows, int E) {
    int e = blockIdx.x * blockDim.x + threadIdx.x;
    if (e < E) atomicAdd(&g_rowptr[rows[e] + 1], 1);
}

// inclusive block scan: 1024 elements per block (256 threads x 4)
__global__ void k_scan_block(int* __restrict__ d, int L, int* __restrict__ bsums) {
    __shared__ int warpsum[8];
    const int t = threadIdx.x, lane = t & 31, wid = t >> 5;
    const int base = blockIdx.x * 1024 + t * 4;
    int v0 = 0, v1 = 0, v2 = 0, v3 = 0;
    if (base + 3 < L) {
        int4 x = *(const int4*)(d + base);
        v0 = x.x; v1 = x.y; v2 = x.z; v3 = x.w;
    } else {
        if (base < L) v0 = d[base];
        if (base + 1 < L) v1 = d[base + 1];
        if (base + 2 < L) v2 = d[base + 2];
    }
    v1 += v0; v2 += v1; v3 += v2;
    int inc = v3;
#pragma unroll
    for (int o = 1; o < 32; o <<= 1) {
        int n = __shfl_up_sync(0xffffffffu, inc, o);
        if (lane >= o) inc += n;
    }
    if (lane == 31) warpsum[wid] = inc;
    __syncthreads();
    if (wid == 0) {
        int s = (lane < 8) ? warpsum[lane] : 0;
#pragma unroll
        for (int o = 1; o < 8; o <<= 1) {
            int n = __shfl_up_sync(0xffffffffu, s, o);
            if (lane >= o) s += n;
        }
        if (lane < 8) warpsum[lane] = s;
    }
    __syncthreads();
    int off = inc - v3;
    if (wid > 0) off += warpsum[wid - 1];
    v0 += off; v1 += off; v2 += off; v3 += off;
    if (base + 3 < L) {
        *(int4*)(d + base) = make_int4(v0, v1, v2, v3);
    } else {
        if (base < L) d[base] = v0;
        if (base + 1 < L) d[base + 1] = v1;
        if (base + 2 < L) d[base + 2] = v2;
    }
    if (t == 255) bsums[blockIdx.x] = v3;
}

__global__ void k_scan_sums(int* __restrict__ bsums, int nb) {
    __shared__ int ws[4];
    const int t = threadIdx.x, lane = t & 31, wid = t >> 5;
    int v = (t < nb) ? bsums[t] : 0;
    int inc = v;
#pragma unroll
    for (int o = 1; o < 32; o <<= 1) {
        int n = __shfl_up_sync(0xffffffffu, inc, o);
        if (lane >= o) inc += n;
    }
    if (lane == 31) ws[wid] = inc;
    __syncthreads();
    if (t == 0) {
        int run = 0;
#pragma unroll
        for (int i = 0; i < 4; i++) { int tmp = ws[i]; ws[i] = run; run += tmp; }
    }
    __syncthreads();
    int excl = inc - v + ws[wid];
    if (t < nb) bsums[t] = excl;
}

__global__ void k_scan_add(int* __restrict__ d, int L) {
    const int b = blockIdx.x;
    if (b == 0) return;
    const int add = g_bsums[b];
    const int base = b * 1024 + threadIdx.x * 4;
#pragma unroll
    for (int j = 0; j < 4; j++)
        if (base + j < L) d[base + j] += add;
}

__global__ void k_scatter(const int* __restrict__ rows, const int* __restrict__ cols,
                          const float* __restrict__ vals, int E) {
    int e = blockIdx.x * blockDim.x + threadIdx.x;
    if (e >= E) return;
    int r = rows[e];
    int idx = g_rowptr[r] + atomicAdd(&g_cursor[r], 1);
    g_edges[idx] = make_int2(cols[e], __float_as_int(vals[e]));
}

// ---------------------------------------------------------------------------
// FP16 GEMM (m16n8k16, fp32 accum), BM=128 x BN=256 x BK=32, 512 threads.
// A fp32 [M,512] read ONCE. Register double-buffered.
__global__ __launch_bounds__(512) void f16_gemm1(
        const float* __restrict__ A, const float* __restrict__ B,
        __half* __restrict__ C, int M, int N, int K) {
    constexpr int BM = 128;
    constexpr int BN = 256;
    constexpr int BK = 32;
    constexpr int WM = 32;
    constexpr int WN = 64;
    constexpr int MFR = 2;
    constexpr int NFR = 8;
    constexpr int AS2 = 20;
    constexpr int BS2 = BN + 8;

    __shared__ __align__(16) __half2 As[BM][AS2];
    __shared__ __align__(16) __half2 Bs[BK / 2][BS2];

    const int tid  = threadIdx.x;
    const int warp = tid >> 5;
    const int lane = tid & 31;
    const int wm = (warp & 3) * WM;
    const int wn = (warp >> 2) * WN;
    const int rowBase = blockIdx.y * BM;

    float acc[MFR][NFR][4];
#pragma unroll
    for (int i = 0; i < MFR; i++)
#pragma unroll
        for (int j = 0; j < NFR; j++)
#pragma unroll
            for (int q = 0; q < 4; q++) acc[i][j][q] = 0.f;

    const int arow = tid >> 2;
    const int acol0 = (tid & 3) * 8;
    const int brow = tid >> 4;
    const int bf40 = tid & 15;
    const int gr = rowBase + arow;
    const bool aok = (gr < M);
    const float* aBase = A + (size_t)gr * K + acol0;
    const float* bBase = B + (size_t)brow * N;

    // --- prologue: prefetch k0 = 0 ---
    float4 pa0 = make_float4(0.f, 0.f, 0.f, 0.f);
    float4 pa1 = make_float4(0.f, 0.f, 0.f, 0.f);
    float4 pb[4];
    if (aok) { pa0 = *(const float4*)aBase; pa1 = *(const float4*)(aBase + 4); }
#pragma unroll
    for (int i = 0; i < 4; i++)
        pb[i] = *(const float4*)(bBase + (bf40 + i * 16) * 4);

    for (int k0 = 0; k0 < K; k0 += BK) {
        // --- store prefetched tile to smem (with f32->f16 conversion) ---
        {
            __half2 h[4];
            h[0] = __floats2half2_rn(pa0.x, pa0.y);
            h[1] = __floats2half2_rn(pa0.z, pa0.w);
            h[2] = __floats2half2_rn(pa1.x, pa1.y);
            h[3] = __floats2half2_rn(pa1.z, pa1.w);
            *(uint4*)&As[arow][acol0 / 2] = *(const uint4*)h;
        }
        {
            __half* bsh = (__half*)&Bs[brow >> 1][0];
            const int hsel = brow & 1;
#pragma unroll
            for (int i = 0; i < 4; i++) {
                const int n = (bf40 + i * 16) * 4;
                bsh[(n + 0) * 2 + hsel] = __float2half_rn(pb[i].x);
                bsh[(n + 1) * 2 + hsel] = __float2half_rn(pb[i].y);
                bsh[(n + 2) * 2 + hsel] = __float2half_rn(pb[i].z);
                bsh[(n + 3) * 2 + hsel] = __float2half_rn(pb[i].w);
            }
        }
        __syncthreads();

        // --- prefetch next tile (overlaps the MMA phase below) ---
        const int kn = k0 + BK;
        if (kn < K) {
            if (aok) {
                pa0 = *(const float4*)(aBase + kn);
                pa1 = *(const float4*)(aBase + kn + 4);
            }
            const float* bp = bBase + (size_t)kn * N;
#pragma unroll
            for (int i = 0; i < 4; i++)
                pb[i] = *(const float4*)(bp + (bf40 + i * 16) * 4);
        }

        // --- MMA phase ---
#pragma unroll
        for (int ks = 0; ks < BK / 16; ks++) {
            uint32_t afr[MFR][4];
            uint32_t bfr[NFR][2];
            const int ar = wm + (lane >> 2);
            const int kb = ks * 8 + (lane & 3);
#pragma unroll
            for (int mi = 0; mi < MFR; mi++) {
                afr[mi][0] = *(const uint32_t*)&As[ar + mi * 16 + 0][kb + 0];
                afr[mi][1] = *(const uint32_t*)&As[ar + mi * 16 + 8][kb + 0];
                afr[mi][2] = *(const uint32_t*)&As[ar + mi * 16 + 0][kb + 4];
                afr[mi][3] = *(const uint32_t*)&As[ar + mi * 16 + 8][kb + 4];
            }
            const int bc = wn + (lane >> 2);
#pragma unroll
            for (int ni = 0; ni < NFR; ni++) {
                bfr[ni][0] = *(const uint32_t*)&Bs[kb + 0][bc + ni * 8];
                bfr[ni][1] = *(const uint32_t*)&Bs[kb + 4][bc + ni * 8];
            }
#pragma unroll
            for (int mi = 0; mi < MFR; mi++)
#pragma unroll
                for (int ni = 0; ni < NFR; ni++)
                    mma_f16(acc[mi][ni], afr[mi], bfr[ni]);
        }
        __syncthreads();
    }

#pragma unroll
    for (int mi = 0; mi < MFR; mi++) {
#pragma unroll
        for (int ni = 0; ni < NFR; ni++) {
            const int r0 = rowBase + wm + mi * 16 + (lane >> 2);
            const int c0 = wn + ni * 8 + 2 * (lane & 3);
            if (r0 < M)
                *(__half2*)(C + (size_t)r0 * N + c0) =
                    __floats2half2_rn(acc[mi][ni][0], acc[mi][ni][1]);
            if (r0 + 8 < M)
                *(__half2*)(C + (size_t)(r0 + 8) * N + c0) =
                    __floats2half2_rn(acc[mi][ni][2], acc[mi][ni][3]);
        }
    }
}

// FP16 GEMM, fp16 A (direct copy), BM=128, BK=32, 256 threads. (GEMM2)
// Register double-buffered like f16_gemm1.
template<int BN, int WARPS_M, int WARPS_N>
__global__ __launch_bounds__(256) void f16_gemm_f16in(
        const __half* __restrict__ A, const float* __restrict__ B,
        __half* __restrict__ C, int M, int N, int K) {
    constexpr int BM = 128;
    constexpr int BK = 32;
    constexpr int WM = BM / WARPS_M;
    constexpr int WN = BN / WARPS_N;
    constexpr int MFR = WM / 16;
    constexpr int NFR = WN / 8;
    constexpr int AS2 = 20;
    constexpr int BS2 = BN + 8;

    __shared__ __align__(16) __half2 As[BM][AS2];
    __shared__ __align__(16) __half2 Bs[BK / 2][BS2];

    const int tid  = threadIdx.x;
    const int warp = tid >> 5;
    const int lane = tid & 31;
    const int wm = (warp % WARPS_M) * WM;
    const int wn = (warp / WARPS_M) * WN;
    const int rowBase = blockIdx.y * BM;
    const int colBase = blockIdx.x * BN;

    float acc[MFR][NFR][4];
#pragma unroll
    for (int i = 0; i < MFR; i++)
#pragma unroll
        for (int j = 0; j < NFR; j++)
#pragma unroll
            for (int q = 0; q < 4; q++) acc[i][j][q] = 0.f;

    const int arow = tid >> 1;
    const int acolh = (tid & 1) * 16;
    const int brow = tid >> 3;
    const int bf40 = tid & 7;
    const int gr = rowBase + arow;
    const bool aok = (gr < M);
    const __half* aBase = A + (size_t)gr * K + acolh;
    const float* bBase = B + (size_t)brow * N + colBase;

    // --- prologue: prefetch k0 = 0 ---
    uint4 pq0 = make_uint4(0, 0, 0, 0), pq1 = make_uint4(0, 0, 0, 0);
    float4 pb[BN / 32];
    if (aok) {
        pq0 = *(const uint4*)aBase;
        pq1 = *(const uint4*)(aBase + 8);
    }
#pragma unroll
    for (int i = 0; i < BN / 32; i++)
        pb[i] = *(const float4*)(bBase + (bf40 + i * 8) * 4);

    for (int k0 = 0; k0 < K; k0 += BK) {
        // --- store prefetched tile to smem ---
        *(uint4*)&As[arow][acolh / 2 + 0] = pq0;
        *(uint4*)&As[arow][acolh / 2 + 4] = pq1;
        {
            __half* bsh = (__half*)&Bs[brow >> 1][0];
            const int hsel = brow & 1;
#pragma unroll
            for (int i = 0; i < BN / 32; i++) {
                const int n = (bf40 + i * 8) * 4;
                bsh[(n + 0) * 2 + hsel] = __float2half_rn(pb[i].x);
                bsh[(n + 1) * 2 + hsel] = __float2half_rn(pb[i].y);
                bsh[(n + 2) * 2 + hsel] = __float2half_rn(pb[i].z);
                bsh[(n + 3) * 2 + hsel] = __float2half_rn(pb[i].w);
            }
        }
        __syncthreads();

        // --- prefetch next tile (overlaps MMA phase) ---
        const int kn = k0 + BK;
        if (kn < K) {
            if (aok) {
                pq0 = *(const uint4*)(aBase + kn);
                pq1 = *(const uint4*)(aBase + kn + 8);
            }
            const float* bp = bBase + (size_t)kn * N;
#pragma unroll
            for (int i = 0; i < BN / 32; i++)
                pb[i] = *(const float4*)(bp + (bf40 + i * 8) * 4);
        }

        // --- MMA phase ---
#pragma unroll
        for (int ks = 0; ks < BK / 16; ks++) {
            uint32_t afr[MFR][4];
            uint32_t bfr[NFR][2];
            const int ar = wm + (lane >> 2);
            const int kb = ks * 8 + (lane & 3);
#pragma unroll
            for (int mi = 0; mi < MFR; mi++) {
                afr[mi][0] = *(const uint32_t*)&As[ar + mi * 16 + 0][kb + 0];
                afr[mi][1] = *(const uint32_t*)&As[ar + mi * 16 + 8][kb + 0];
                afr[mi][2] = *(const uint32_t*)&As[ar + mi * 16 + 0][kb + 4];
                afr[mi][3] = *(const uint32_t*)&As[ar + mi * 16 + 8][kb + 4];
            }
            const int bc = wn + (lane >> 2);
#pragma unroll
            for (int ni = 0; ni < NFR; ni++) {
                bfr[ni][0] = *(const uint32_t*)&Bs[kb + 0][bc + ni * 8];
                bfr[ni][1] = *(const uint32_t*)&Bs[kb + 4][bc + ni * 8];
            }
#pragma unroll
            for (int mi = 0; mi < MFR; mi++)
#pragma unroll
                for (int ni = 0; ni < NFR; ni++)
                    mma_f16(acc[mi][ni], afr[mi], bfr[ni]);
        }
        __syncthreads();
    }

#pragma unroll
    for (int mi = 0; mi < MFR; mi++) {
#pragma unroll
        for (int ni = 0; ni < NFR; ni++) {
            const int r0 = rowBase + wm + mi * 16 + (lane >> 2);
            const int c0 = colBase + wn + ni * 8 + 2 * (lane & 3);
            if (r0 < M)
                *(__half2*)(C + (size_t)r0 * N + c0) =
                    __floats2half2_rn(acc[mi][ni][0], acc[mi][ni][1]);
            if (r0 + 8 < M)
                *(__half2*)(C + (size_t)(r0 + 8) * N + c0) =
                    __floats2half2_rn(acc[mi][ni][2], acc[mi][ni][3]);
        }
    }
}

// ---------------------------------------------------------------------------
// CSR SpMM, F=256, fp16 source (R7 form). One warp per row; lane owns 8 halfs.
__global__ void spmm_csr_f256h(const __half* __restrict__ X, const float* __restrict__ bias,
                               __half* __restrict__ Y) {
    const int r = (blockIdx.x * blockDim.x + threadIdx.x) >> 5;
    const int lane = threadIdx.x & 31;
    if (r >= NNODE) return;
    const int start = g_rowptr[r];
    const int end   = g_rowptr[r + 1];
    float acc[8];
#pragma unroll
    for (int i = 0; i < 8; i++) acc[i] = 0.f;
    const uint4* Xb = (const uint4*)X + lane;
    for (int base = start; base < end; base += 32) {
        const int m = min(32, end - base);
        int2 ev = make_int2(0, 0);
        if (lane < m) ev = g_edges[base + lane];
#pragma unroll 4
        for (int j = 0; j < m; j++) {
            const int   cj = __shfl_sync(0xffffffffu, ev.x, j);
            const float vj = __int_as_float(__shfl_sync(0xffffffffu, ev.y, j));
            uint4 q = __ldg(Xb + (size_t)cj * 32);
            const __half2* hp = (const __half2*)&q;
#pragma unroll
            for (int i = 0; i < 4; i++) {
                float2 f = __half22float2(hp[i]);
                acc[i * 2 + 0] = fmaf(vj, f.x, acc[i * 2 + 0]);
                acc[i * 2 + 1] = fmaf(vj, f.y, acc[i * 2 + 1]);
            }
        }
    }
    float4 b0 = __ldg((const float4*)bias + lane * 2);
    float4 b1 = __ldg((const float4*)bias + lane * 2 + 1);
    float bb[8] = {b0.x, b0.y, b0.z, b0.w, b1.x, b1.y, b1.z, b1.w};
    __half2 o[4];
#pragma unroll
    for (int i = 0; i < 4; i++)
        o[i] = __floats2half2_rn(fmaxf(acc[i * 2] + bb[i * 2], 0.f),
                                 fmaxf(acc[i * 2 + 1] + bb[i * 2 + 1], 0.f));
    uint4 ov = *(const uint4*)o;
    stcs_u4((uint4*)Y + (size_t)r * 32 + lane, ov);
}

// CSR SpMM F=64 (fp16 source) fused with bias + log_softmax (R7 form).
__global__ void spmm_csr_f64h_ls(const __half* __restrict__ X, const float* __restrict__ bias,
                                 float* __restrict__ out) {
    const int r = (blockIdx.x * blockDim.x + threadIdx.x) >> 5;
    const int lane = threadIdx.x & 31;
    if (r >= NNODE) return;
    const int start = g_rowptr[r];
    const int end   = g_rowptr[r + 1];
    float2 acc = make_float2(0.f, 0.f);
    const uint32_t* Xb = (const uint32_t*)X + lane;
    for (int base = start; base < end; base += 32) {
        const int m = min(32, end - base);
        int2 ev = make_int2(0, 0);
        if (lane < m) ev = g_edges[base + lane];
#pragma unroll 4
        for (int j = 0; j < m; j++) {
            const int   cj = __shfl_sync(0xffffffffu, ev.x, j);
            const float vj = __int_as_float(__shfl_sync(0xffffffffu, ev.y, j));
            uint32_t q = __ldg(Xb + (size_t)cj * 32);
            float2 xs = __half22float2(*(const __half2*)&q);
            acc.x = fmaf(vj, xs.x, acc.x);
            acc.y = fmaf(vj, xs.y, acc.y);
        }
    }
    float2 bb = __ldg((const float2*)bias + lane);
    float v0 = acc.x + bb.x;
    float v1 = acc.y + bb.y;
    float mx = fmaxf(v0, v1);
#pragma unroll
    for (int o = 16; o; o >>= 1) mx = fmaxf(mx, __shfl_xor_sync(0xffffffffu, mx, o));
    float s = __expf(v0 - mx) + __expf(v1 - mx);
#pragma unroll
    for (int o = 16; o; o >>= 1) s += __shfl_xor_sync(0xffffffffu, s, o);
    float lse = mx + __logf(s);
    *(float2*)(out + (size_t)r * 64 + lane * 2) = make_float2(v0 - lse, v1 - lse);
}

// ---------------------------------------------------------------------------
extern "C" void kernel_launch(void* const* d_in, const int* in_sizes, int n_in,
                              void* d_out, int out_size) {
    const float* x    = (const float*)d_in[0];
    const int*   erow = (const int*)d_in[1];
    const int*   ecol = (const int*)d_in[2];
    const float* eval_ = (const float*)d_in[3];
    const float* W1   = (const float*)d_in[4];
    const float* b1   = (const float*)d_in[5];
    const float* W2   = (const float*)d_in[6];
    const float* b2   = (const float*)d_in[7];
    float* out = (float*)d_out;

    const int E = in_sizes[1];
    const int M = in_sizes[0] / NF;  // 100000

    __half *xw1, *h, *hw2;
    int *rowptr, *bsums;
    cudaGetSymbolAddress((void**)&xw1, g_xw1);
    cudaGetSymbolAddress((void**)&h, g_h);
    cudaGetSymbolAddress((void**)&hw2, g_hw2);
    cudaGetSymbolAddress((void**)&rowptr, g_rowptr);
    cudaGetSymbolAddress((void**)&bsums, g_bsums);

    const int L = NNODE + 1;
    const int nscan = (L + 1023) / 1024;  // 98

    // One-time side resources (host-side only; no device memory involved).
    static cudaStream_t s2 = nullptr;
    static cudaEvent_t evFork = nullptr, evJoin = nullptr;
    if (!s2) {
        cudaStreamCreateWithFlags(&s2, cudaStreamNonBlocking);
        cudaEventCreateWithFlags(&evFork, cudaEventDisableTiming);
        cudaEventCreateWithFlags(&evJoin, cudaEventDisableTiming);
    }

    // Fork: CSR build on s2, concurrent with GEMM1 on the main stream.
    cudaEventRecord(evFork, 0);
    cudaStreamWaitEvent(s2, evFork, 0);

    // --- CSR build (stream s2) ---
    k_zero_csr<<<(NNODE + 256) / 256, 256, 0, s2>>>();
    k_hist<<<(E + 255) / 256, 256, 0, s2>>>(erow, E);
    k_scan_block<<<nscan, 256, 0, s2>>>(rowptr, L, bsums);
    k_scan_sums<<<1, 128, 0, s2>>>(bsums, nscan);
    k_scan_add<<<nscan, 256, 0, s2>>>(rowptr, L);
    k_scatter<<<(E + 255) / 256, 256, 0, s2>>>(erow, ecol, eval_, E);
    cudaEventRecord(evJoin, s2);

    // --- layer 1 GEMM (main stream, concurrent with CSR build) ---
    f16_gemm1<<<dim3(1, (M + 127) / 128), 512>>>(x, W1, xw1, M, NH, NF);

    // Join: spmm1 needs both GEMM1 and the CSR structures.
    cudaStreamWaitEvent(0, evJoin, 0);

    // spmm1 (CSR gather, fp16 source L2-resident) + fused bias/relu
    {
        int blocks = (NNODE * 32 + 255) / 256;
        spmm_csr_f256h<<<blocks, 256>>>(xw1, b1, h);
    }

    // layer 2: HW2 = h @ W2  (fp16 tensor cores, fp16 A direct)
    f16_gemm_f16in<64, 4, 2><<<dim3(NC / 64, (M + 127) / 128), 256>>>(h, W2, hw2, M, NC, NH);

    // spmm2 (CSR gather, fp16 source) + fused bias + log_softmax
    {
        int blocks = (NNODE * 32 + 255) / 256;
        spmm_csr_f64h_ls<<<blocks, 256>>>(hw2, b2, out);
    }
}